// round 1
// baseline (speedup 1.0000x reference)
#include <cuda_runtime.h>

#define NNODES 256
#define FIN 6
#define HDIM 32
#define EMBD 32
#define VECD 26
#define DPIV 512
#define BATCH 1024
#define EMAX 4096
#define STRIDE 36   // padded row stride: float4-aligned for all rows, (4c+f)%32 bank spread

__device__ int g_row_ptr[NNODES + 1];
__device__ int g_col[EMAX];
__device__ float g_val[EMAX];

// ---------------------------------------------------------------------------
// Prep: degrees -> symmetric norm, build CSR by dst. One CTA, 256 threads.
// ---------------------------------------------------------------------------
__global__ void prep_kernel(const int* __restrict__ src, const int* __restrict__ dst, int E) {
    __shared__ float degO[NNODES], degI[NNODES];
    __shared__ int cur[NNODES];
    int t = threadIdx.x;
    degO[t] = 0.f; degI[t] = 0.f;
    __syncthreads();
    for (int e = t; e < E; e += NNODES) {
        atomicAdd(&degO[src[e]], 1.f);
        atomicAdd(&degI[dst[e]], 1.f);
    }
    __syncthreads();
    if (t == 0) {
        int acc = 0;
        for (int n = 0; n < NNODES; n++) {
            g_row_ptr[n] = acc; cur[n] = acc;
            acc += (int)degI[n];
        }
        g_row_ptr[NNODES] = acc;
    }
    __syncthreads();
    float io = degO[t] > 0.f ? rsqrtf(degO[t]) : 0.f;
    float ii = degI[t] > 0.f ? rsqrtf(degI[t]) : 0.f;
    __syncthreads();
    degO[t] = io; degI[t] = ii;
    __syncthreads();
    for (int e = t; e < E; e += NNODES) {
        int s_ = src[e], d_ = dst[e];
        float nv = degO[s_] * degI[d_];
        int pos = atomicAdd(&cur[d_], 1);
        g_col[pos] = s_;
        g_val[pos] = nv;
    }
}

// ---------------------------------------------------------------------------
// Main: one CTA per batch element, thread n = node n.
// Uses (A@x)@W == A@(x@W): apply W1 first, then 3x [gather -> bias/relu -> W].
// ---------------------------------------------------------------------------
__global__ __launch_bounds__(NNODES, 2)
void gnn_kernel(const float* __restrict__ gf, const float* __restrict__ vec,
                const float* __restrict__ W1, const float* __restrict__ b1,
                const float* __restrict__ W2, const float* __restrict__ b2,
                const float* __restrict__ W3, const float* __restrict__ b3,
                const float* __restrict__ We, const float* __restrict__ be,
                const float* __restrict__ Wpi, const float* __restrict__ bpi,
                const float* __restrict__ Wvf, const float* __restrict__ bvf,
                float* __restrict__ out)
{
    extern __shared__ float s[];
    float* bufA = s;                          // 256*36
    float* bufB = bufA + NNODES * STRIDE;     // 256*36
    float* sW1  = bufB + NNODES * STRIDE;     // 6*32
    float* sW2  = sW1 + FIN * HDIM;           // 32*32
    float* sW3  = sW2 + HDIM * HDIM;          // 32*32
    float* sWe  = sW3 + HDIM * HDIM;          // 32*32
    float* sb   = sWe + HDIM * EMBD;          // b1|b2|b3|be (4*32)
    float* comb = sb + 4 * HDIM;              // 64

    int n = threadIdx.x;
    int b = blockIdx.x;

    // cooperative weight staging
    for (int i = n; i < FIN * HDIM; i += NNODES) sW1[i] = W1[i];
    for (int i = n; i < HDIM * HDIM; i += NNODES) {
        sW2[i] = W2[i]; sW3[i] = W3[i]; sWe[i] = We[i];
    }
    if (n < HDIM) {
        sb[n] = b1[n]; sb[32 + n] = b2[n]; sb[64 + n] = b3[n]; sb[96 + n] = be[n];
    }

    float x[FIN];
    const float* gr = gf + (size_t)b * NNODES * FIN + n * FIN;
#pragma unroll
    for (int f = 0; f < FIN; f++) x[f] = gr[f];
    __syncthreads();

    // y0 = x @ W1 -> bufA
    {
        float y[HDIM];
#pragma unroll
        for (int f = 0; f < HDIM; f++) y[f] = 0.f;
#pragma unroll
        for (int k = 0; k < FIN; k++) {
            float xk = x[k];
#pragma unroll
            for (int f = 0; f < HDIM; f++) y[f] += xk * sW1[k * HDIM + f];
        }
        float4* row = (float4*)(bufA + n * STRIDE);
#pragma unroll
        for (int q = 0; q < 8; q++)
            row[q] = make_float4(y[4*q], y[4*q+1], y[4*q+2], y[4*q+3]);
    }
    __syncthreads();

    int rs = g_row_ptr[n], re = g_row_ptr[n + 1];
    float h[HDIM];

#pragma unroll
    for (int l = 0; l < 3; l++) {
        float* sbuf = (l & 1) ? bufB : bufA;
        float agg[HDIM];
#pragma unroll
        for (int f = 0; f < HDIM; f++) agg[f] = 0.f;
        for (int j = rs; j < re; j++) {
            float v = g_val[j];
            const float4* row = (const float4*)(sbuf + g_col[j] * STRIDE);
#pragma unroll
            for (int q = 0; q < 8; q++) {
                float4 r = row[q];
                agg[4*q]   += v * r.x; agg[4*q+1] += v * r.y;
                agg[4*q+2] += v * r.z; agg[4*q+3] += v * r.w;
            }
        }
#pragma unroll
        for (int f = 0; f < HDIM; f++)
            h[f] = fmaxf(agg[f] + sb[l * 32 + f], 0.f);

        if (l < 2) {
            const float* W = (l == 0) ? sW2 : sW3;
            float y[HDIM];
#pragma unroll
            for (int f = 0; f < HDIM; f++) y[f] = 0.f;
#pragma unroll
            for (int k = 0; k < HDIM; k++) {
                float hk = h[k];
                const float4* Wr = (const float4*)(W + k * HDIM);
#pragma unroll
                for (int q = 0; q < 8; q++) {
                    float4 w = Wr[q];
                    y[4*q]   += hk * w.x; y[4*q+1] += hk * w.y;
                    y[4*q+2] += hk * w.z; y[4*q+3] += hk * w.w;
                }
            }
            float* dbuf = (l & 1) ? bufA : bufB;
            float4* row = (float4*)(dbuf + n * STRIDE);
#pragma unroll
            for (int q = 0; q < 8; q++)
                row[q] = make_float4(y[4*q], y[4*q+1], y[4*q+2], y[4*q+3]);
        } else {
            // final h -> bufB for pooling
            float4* row = (float4*)(bufB + n * STRIDE);
#pragma unroll
            for (int q = 0; q < 8; q++)
                row[q] = make_float4(h[4*q], h[4*q+1], h[4*q+2], h[4*q+3]);
        }
        __syncthreads();
    }

    // mean over nodes: tree reduction in bufB
    for (int step = 128; step >= 1; step >>= 1) {
        if (n < step) {
            float4* a = (float4*)(bufB + n * STRIDE);
            const float4* c = (const float4*)(bufB + (n + step) * STRIDE);
#pragma unroll
            for (int q = 0; q < 8; q++) {
                float4 av = a[q], cv = c[q];
                a[q] = make_float4(av.x + cv.x, av.y + cv.y, av.z + cv.z, av.w + cv.w);
            }
        }
        __syncthreads();
    }

    // emb = (hg/256) @ We + be ; comb = [vector | emb]
    if (n < EMBD) {
        float e = sb[96 + n];
#pragma unroll
        for (int k = 0; k < HDIM; k++)
            e += (bufB[k] * (1.0f / 256.0f)) * sWe[k * EMBD + n];
        comb[VECD + n] = e;
    }
    if (n < VECD) comb[n] = vec[(size_t)b * VECD + n];
    __syncthreads();

    // heads: pi / vf, 512 outputs each; thread handles j = n and n+256
#pragma unroll
    for (int rep = 0; rep < 2; rep++) {
        int j = n + rep * NNODES;
        float a = bpi[j], av = bvf[j];
#pragma unroll 2
        for (int k = 0; k < VECD + EMBD; k++) {
            float c = comb[k];
            a  += c * Wpi[k * DPIV + j];
            av += c * Wvf[k * DPIV + j];
        }
        out[(size_t)b * DPIV + j] = fmaxf(a, 0.f);
        out[(size_t)BATCH * DPIV + (size_t)b * DPIV + j] = fmaxf(av, 0.f);
    }
}

extern "C" void kernel_launch(void* const* d_in, const int* in_sizes, int n_in,
                              void* d_out, int out_size) {
    const float* gf  = (const float*)d_in[0];
    const float* vec = (const float*)d_in[1];
    const int*   src = (const int*)d_in[2];
    const int*   dst = (const int*)d_in[3];
    const float* W1  = (const float*)d_in[4];
    const float* b1  = (const float*)d_in[5];
    const float* W2  = (const float*)d_in[6];
    const float* b2  = (const float*)d_in[7];
    const float* W3  = (const float*)d_in[8];
    const float* b3  = (const float*)d_in[9];
    const float* We  = (const float*)d_in[10];
    const float* be  = (const float*)d_in[11];
    const float* Wpi = (const float*)d_in[12];
    const float* bpi = (const float*)d_in[13];
    const float* Wvf = (const float*)d_in[14];
    const float* bvf = (const float*)d_in[15];

    int E = in_sizes[2];
    if (E > EMAX) E = EMAX;

    prep_kernel<<<1, NNODES>>>(src, dst, E);

    int smem = (2 * NNODES * STRIDE + FIN * HDIM + 3 * HDIM * HDIM + 4 * HDIM + 64) * (int)sizeof(float);
    cudaFuncSetAttribute(gnn_kernel, cudaFuncAttributeMaxDynamicSharedMemorySize, smem);
    gnn_kernel<<<BATCH, NNODES, smem>>>(gf, vec, W1, b1, W2, b2, W3, b3,
                                        We, be, Wpi, bpi, Wvf, bvf, (float*)d_out);
}